// round 4
// baseline (speedup 1.0000x reference)
#include <cuda_runtime.h>
#include <cuda_bf16.h>
#include <cstdint>

// ---------------------------------------------------------------------------
// Problem constants
// ---------------------------------------------------------------------------
constexpr int BROWS = 1024;    // batch (M)
constexpr int DIM   = 4096;    // in features (K)
constexpr int NCLS  = 50257;   // classes (N)
constexpr int LPAD  = 50260;   // padded scratch row stride (mult of 4)

constexpr int MT = 256;        // CTA tile M
constexpr int NT = 128;        // CTA tile N
constexpr int KT = 32;         // K per stage
constexpr int K_ITERS = DIM / KT;               // 128
constexpr int NTILES_N = (NCLS + NT - 1) / NT;  // 393

// SMEM stage layout (bytes, relative to stage base):
//   A_hi[256][32]bf16 : 16384
//   A_lo[256][32]bf16 : 16384
//   B_f32[128][32]f32 : 16384 (linear 128B rows)
//   B_hi[128][32]bf16 :  8192 (swizzled 64B rows)
//   B_lo[128][32]bf16 :  8192
constexpr uint32_t AH_OFF   = 0;
constexpr uint32_t AL_OFF   = 16384;
constexpr uint32_t BF32_OFF = 32768;
constexpr uint32_t BH_OFF   = 49152;
constexpr uint32_t BL_OFF   = 57344;
constexpr uint32_t STAGE_B  = 65536;
constexpr int NSTAGE = 3;
constexpr uint32_t SMEM_TOTAL = NSTAGE * STAGE_B;   // 192 KB

// ---------------------------------------------------------------------------
// Device scratch (no allocations allowed). 256B-aligned.
// ---------------------------------------------------------------------------
__device__ __align__(256) float g_exp[(size_t)BROWS * LPAD];        // ~206 MB
__device__ __align__(256) float g_rowsum[BROWS];
__device__ __align__(256) __nv_bfloat16 g_xh[(size_t)BROWS * DIM];  // 8 MB
__device__ __align__(256) __nv_bfloat16 g_xl[(size_t)BROWS * DIM];  // 8 MB

// ---------------------------------------------------------------------------
// PTX helpers (sm_103-safe: no tcgen05)
// ---------------------------------------------------------------------------
__device__ __forceinline__ uint32_t smem_u32(const void* p) {
    uint32_t r;
    asm("{ .reg .u64 t; cvta.to.shared.u64 t, %1; cvt.u32.u64 %0, t; }"
        : "=r"(r) : "l"(p));
    return r;
}

__device__ __forceinline__ void cp16(uint32_t dst, const void* src) {
    asm volatile("cp.async.cg.shared.global [%0], [%1], 16;"
                 :: "r"(dst), "l"(src));
}
__device__ __forceinline__ void cp16z(uint32_t dst, const void* src, uint32_t sz) {
    asm volatile("cp.async.cg.shared.global [%0], [%1], 16, %2;"
                 :: "r"(dst), "l"(src), "r"(sz));
}
__device__ __forceinline__ void cp_commit() {
    asm volatile("cp.async.commit_group;" ::: "memory");
}
template <int N>
__device__ __forceinline__ void cp_wait() {
    asm volatile("cp.async.wait_group %0;" :: "n"(N) : "memory");
}

__device__ __forceinline__ void ldsm4(uint32_t* r, uint32_t addr) {
    asm volatile("ldmatrix.sync.aligned.m8n8.x4.shared.b16 {%0,%1,%2,%3}, [%4];"
                 : "=r"(r[0]), "=r"(r[1]), "=r"(r[2]), "=r"(r[3]) : "r"(addr));
}

__device__ __forceinline__ void mma16816(float* c, const uint32_t* a, const uint32_t* b) {
    asm volatile(
        "mma.sync.aligned.m16n8k16.row.col.f32.bf16.bf16.f32 "
        "{%0,%1,%2,%3}, {%4,%5,%6,%7}, {%8,%9}, {%0,%1,%2,%3};"
        : "+f"(c[0]), "+f"(c[1]), "+f"(c[2]), "+f"(c[3])
        : "r"(a[0]), "r"(a[1]), "r"(a[2]), "r"(a[3]), "r"(b[0]), "r"(b[1]));
}

// Swizzled smem offset for [row][chunk16B] with 64B rows; conflict-free ldmatrix
__device__ __forceinline__ uint32_t swz(uint32_t row, uint32_t ck) {
    return row * 64u + ((ck ^ ((row >> 1) & 3u)) << 4);
}

__device__ __forceinline__ uint32_t pack2(float a, float b) {
    __nv_bfloat162 v(__float2bfloat16(a), __float2bfloat16(b));
    return *reinterpret_cast<uint32_t*>(&v);
}

// ---------------------------------------------------------------------------
// Pre-split x: fp32 -> bf16 hi + bf16 lo (residual). ~32MB traffic.
// ---------------------------------------------------------------------------
__global__ void __launch_bounds__(256) split_kernel(
    const float* __restrict__ in, __nv_bfloat16* __restrict__ hi,
    __nv_bfloat16* __restrict__ lo, int n4) {
    for (int i = blockIdx.x * blockDim.x + threadIdx.x; i < n4;
         i += gridDim.x * blockDim.x) {
        const float4 f = reinterpret_cast<const float4*>(in)[i];
        float h0 = __bfloat162float(__float2bfloat16(f.x));
        float h1 = __bfloat162float(__float2bfloat16(f.y));
        float h2 = __bfloat162float(__float2bfloat16(f.z));
        float h3 = __bfloat162float(__float2bfloat16(f.w));
        uint2 hv, lv;
        hv.x = pack2(f.x, f.y); hv.y = pack2(f.z, f.w);
        lv.x = pack2(f.x - h0, f.y - h1); lv.y = pack2(f.z - h2, f.w - h3);
        reinterpret_cast<uint2*>(hi)[i] = hv;
        reinterpret_cast<uint2*>(lo)[i] = lv;
    }
}

// ---------------------------------------------------------------------------
// GEMM: e = exp(x @ W^T + b) into g_exp, row sums into g_rowsum (atomics).
// 3-pass bf16 split, fp32 accum. CTA 256x128, 8 warps (4m x 2n).
// W is read as fp32 via cp.async and split to bf16 hi/lo in-kernel.
// ---------------------------------------------------------------------------
__global__ void __launch_bounds__(256, 1) svp_gemm(
    const float* __restrict__ W, const float* __restrict__ bias) {
    extern __shared__ char smem[];
    const uint32_t sb = smem_u32(smem);
    const int tid  = threadIdx.x;
    const int wid  = tid >> 5;
    const int lane = tid & 31;
    const int wm = wid >> 1;          // 0..3
    const int wn = wid & 1;           // 0..1

    const int m0 = blockIdx.x * MT;
    const int n0 = blockIdx.y * NT;

    // ---- stage loader: A (pre-split bf16) + B (fp32 staging) ----
    auto load_stage = [&](int kc, int slot) {
        const uint32_t st = sb + (uint32_t)slot * STAGE_B;
        const int kbase = kc * KT;
        // A: 256 rows x 4 chunks of 16B, hi+lo
        #pragma unroll
        for (int i = 0; i < 4; ++i) {
            const int id  = tid + i * 256;       // 0..1023
            const int row = id >> 2;
            const int ck  = id & 3;
            const uint32_t d = st + swz((uint32_t)row, (uint32_t)ck);
            const size_t gi = (size_t)(m0 + row) * DIM + kbase + ck * 8;
            cp16(d + AH_OFF, g_xh + gi);
            cp16(d + AL_OFF, g_xl + gi);
        }
        // B fp32: 128 rows x 8 chunks of 16B (4 floats), linear rows, zero past NCLS
        #pragma unroll
        for (int i = 0; i < 4; ++i) {
            const int id  = tid + i * 256;       // 0..1023
            const int row = id >> 3;
            const int q   = id & 7;
            const int n   = n0 + row;
            const uint32_t sz = (n < NCLS) ? 16u : 0u;
            const int nn = (n < NCLS) ? n : 0;
            const uint32_t d = st + BF32_OFF + (uint32_t)(row * 128 + q * 16);
            cp16z(d, W + (size_t)nn * DIM + kbase + q * 4, sz);
        }
        cp_commit();
    };

    // ---- prologue ----
    load_stage(0, 0);
    load_stage(1, 1);
    load_stage(2, 2);

    float acc[4][8][4];
    #pragma unroll
    for (int a = 0; a < 4; ++a)
        #pragma unroll
        for (int b = 0; b < 8; ++b)
            #pragma unroll
            for (int c = 0; c < 4; ++c) acc[a][b][c] = 0.f;

    // ---- main loop ----
    for (int it = 0; it < K_ITERS; ++it) {
        cp_wait<NSTAGE - 1>();
        __syncthreads();

        const uint32_t stA = sb + (uint32_t)(it % NSTAGE) * STAGE_B;
        char* stage = smem + (size_t)(it % NSTAGE) * STAGE_B;

        // ---- convert B fp32 -> bf16 hi/lo (swizzled) ----
        // thread t handles float4 idx t, t+256, t+512, t+768 (bank-clean reads)
        {
            const float4* bf = reinterpret_cast<const float4*>(stage + BF32_OFF);
            #pragma unroll
            for (int p = 0; p < 4; ++p) {
                const int v = tid + p * 256;       // float4 index, 0..1023
                const float4 f = bf[v];
                const int row = v >> 3;
                const int j   = v & 7;             // float4 within row
                const int ck  = j >> 1;            // 16B bf16 chunk
                const int hb  = (j & 1) * 8;       // byte offset within chunk
                const uint32_t o = swz((uint32_t)row, (uint32_t)ck) + hb;
                float h0 = __bfloat162float(__float2bfloat16(f.x));
                float h1 = __bfloat162float(__float2bfloat16(f.y));
                float h2 = __bfloat162float(__float2bfloat16(f.z));
                float h3 = __bfloat162float(__float2bfloat16(f.w));
                uint2 hv, lv;
                hv.x = pack2(f.x, f.y); hv.y = pack2(f.z, f.w);
                lv.x = pack2(f.x - h0, f.y - h1);
                lv.y = pack2(f.z - h2, f.w - h3);
                *reinterpret_cast<uint2*>(stage + BH_OFF + o) = hv;
                *reinterpret_cast<uint2*>(stage + BL_OFF + o) = lv;
            }
        }
        __syncthreads();

        const uint32_t stBh = stA + BH_OFF;
        const uint32_t stBl = stA + BL_OFF;

        #pragma unroll
        for (int kk = 0; kk < 2; ++kk) {     // two k16 steps per stage
            // A fragments (hi & lo): 4 m-tiles of 16
            uint32_t ah[4][4], al[4][4];
            {
                const uint32_t r = (uint32_t)(wm * 64 + (lane & 15));
                const uint32_t c = (uint32_t)(kk * 2 + (lane >> 4));
                #pragma unroll
                for (int mt = 0; mt < 4; ++mt) {
                    const uint32_t ad = stA + swz(r + mt * 16u, c);
                    ldsm4(ah[mt], ad + AH_OFF);
                    ldsm4(al[mt], ad + AL_OFF);
                }
            }
            #pragma unroll
            for (int h = 0; h < 2; ++h) {
                uint32_t bh[2][4], bl[2][4];
                {
                    const uint32_t rbase =
                        (uint32_t)(wn * 64 + h * 32 + (lane & 7) + ((lane & 16) >> 1));
                    const uint32_t c = (uint32_t)(kk * 2 + ((lane >> 3) & 1));
                    #pragma unroll
                    for (int q = 0; q < 2; ++q) {
                        const uint32_t o = swz(rbase + q * 16u, c);
                        ldsm4(bh[q], stBh + o);
                        ldsm4(bl[q], stBl + o);
                    }
                }
                // term-major: accumulator reuse distance = 16 MMAs (no RAW chains)
                #pragma unroll
                for (int mt = 0; mt < 4; ++mt)
                    #pragma unroll
                    for (int q = 0; q < 2; ++q)
                        #pragma unroll
                        for (int t = 0; t < 2; ++t)
                            mma16816(acc[mt][h * 4 + q * 2 + t], ah[mt], &bh[q][t * 2]);
                #pragma unroll
                for (int mt = 0; mt < 4; ++mt)
                    #pragma unroll
                    for (int q = 0; q < 2; ++q)
                        #pragma unroll
                        for (int t = 0; t < 2; ++t)
                            mma16816(acc[mt][h * 4 + q * 2 + t], ah[mt], &bl[q][t * 2]);
                #pragma unroll
                for (int mt = 0; mt < 4; ++mt)
                    #pragma unroll
                    for (int q = 0; q < 2; ++q)
                        #pragma unroll
                        for (int t = 0; t < 2; ++t)
                            mma16816(acc[mt][h * 4 + q * 2 + t], al[mt], &bh[q][t * 2]);
            }
        }

        __syncthreads();
        if (it + NSTAGE < K_ITERS) load_stage(it + NSTAGE, it % NSTAGE);
        else cp_commit();   // keep group counting uniform
    }

    // ---- epilogue: e = exp(acc + bias); store; warp-reduce row sums ----
    #pragma unroll
    for (int mt = 0; mt < 4; ++mt) {
        const int r0 = m0 + wm * 64 + mt * 16 + (lane >> 2);
        float rs0 = 0.f, rs1 = 0.f;     // partial sums for rows r0, r0+8
        #pragma unroll
        for (int nt = 0; nt < 8; ++nt) {
            const int n = n0 + wn * 64 + nt * 8 + (lane & 3) * 2;
            if (n >= NCLS) continue;
            const float b0 = __ldg(bias + n);
            const bool ok1 = (n + 1) < NCLS;
            const float b1 = ok1 ? __ldg(bias + n + 1) : 0.f;
            float* o0 = g_exp + (size_t)r0 * LPAD + n;
            float* o1 = g_exp + (size_t)(r0 + 8) * LPAD + n;
            const float* cc = acc[mt][nt];
            const float e00 = __expf(cc[0] + b0);
            const float e10 = __expf(cc[2] + b0);
            if (ok1) {
                const float e01 = __expf(cc[1] + b1);
                const float e11 = __expf(cc[3] + b1);
                *reinterpret_cast<float2*>(o0) = make_float2(e00, e01);
                *reinterpret_cast<float2*>(o1) = make_float2(e10, e11);
                rs0 += e00 + e01;
                rs1 += e10 + e11;
            } else {
                o0[0] = e00; o1[0] = e10;
                rs0 += e00; rs1 += e10;
            }
        }
        // reduce across the 4 lanes sharing each row (lane&3 group)
        rs0 += __shfl_xor_sync(0xFFFFFFFF, rs0, 1);
        rs0 += __shfl_xor_sync(0xFFFFFFFF, rs0, 2);
        rs1 += __shfl_xor_sync(0xFFFFFFFF, rs1, 1);
        rs1 += __shfl_xor_sync(0xFFFFFFFF, rs1, 2);
        if ((lane & 3) == 0) {
            atomicAdd(g_rowsum + r0, rs0);
            atomicAdd(g_rowsum + r0 + 8, rs1);
        }
    }
}

// ---------------------------------------------------------------------------
// Normalize: out = e * (1 / rowsum). One CTA per row.
// ---------------------------------------------------------------------------
__global__ void __launch_bounds__(256) svp_norm(float* __restrict__ out) {
    const int tid = threadIdx.x;
    const int row = blockIdx.x;
    const float* e = g_exp + (size_t)row * LPAD;
    float* o = out + (size_t)row * NCLS;
    const float inv = 1.f / g_rowsum[row];
    for (int i = tid; i < NCLS; i += 256) o[i] = e[i] * inv;
}

// ---------------------------------------------------------------------------
// Launch
// ---------------------------------------------------------------------------
extern "C" void kernel_launch(void* const* d_in, const int* in_sizes, int n_in,
                              void* d_out, int out_size) {
    const float* x = (const float*)d_in[0];   // [1024, 4096]
    const float* W = (const float*)d_in[1];   // [50257, 4096]
    const float* b = (const float*)d_in[2];   // [50257]
    float* out = (float*)d_out;               // [1024, 50257]

    __nv_bfloat16 *xh, *xl;
    float* rowsum;
    cudaGetSymbolAddress((void**)&xh, g_xh);
    cudaGetSymbolAddress((void**)&xl, g_xl);
    cudaGetSymbolAddress((void**)&rowsum, g_rowsum);

    cudaMemsetAsync(rowsum, 0, BROWS * sizeof(float));
    split_kernel<<<512, 256>>>(x, xh, xl, BROWS * DIM / 4);

    cudaFuncSetAttribute(svp_gemm, cudaFuncAttributeMaxDynamicSharedMemorySize,
                         SMEM_TOTAL);
    dim3 grid(BROWS / MT, NTILES_N);   // (4, 393), m fastest for W reuse
    svp_gemm<<<grid, 256, SMEM_TOTAL>>>(W, b);

    svp_norm<<<BROWS, 256>>>(out);
}